// round 4
// baseline (speedup 1.0000x reference)
#include <cuda_runtime.h>
#include <cuda_bf16.h>
#include <stdint.h>

// WeightsDropout: per row of [8192,1,4096] f32, zero the 2048 smallest
// (stable-argsort tie-break by index), softmax over survivors.
//
// One CTA (512 thr) per row; row in registers (2 float4/thread).
// Fast path (uniform-like data): single fused pass computes max,
// count(v < 0.4375), a 256-bin histogram over [0.4375, 0.5625), AND pools
// the in-window keys (float_bits<<12 | idx == stable-sort order).
// Warp 0 scans the histogram for the rank-2048 bin, filters pooled keys
// for that bin (~2), and picks the exact threshold key. Hot path is a
// single (val,idx) compare per element.
// Fallback (arbitrary data, pool overflow, boundary outside window):
// exact 6-level radix-select on monotone 44-bit keys.

namespace {

constexpr int N        = 4096;
constexpr int KDROP    = 2048;
constexpr int THREADS  = 512;
constexpr int VEC      = N / 4 / THREADS;   // 2 float4 per thread
constexpr int NWARP    = THREADS / 32;      // 16
constexpr int NB       = 256;
constexpr int CAND_CAP = 1024;              // in-window pool (exp ~512, +24 sigma)
constexpr int C2_CAP   = 64;                // boundary-bin keys (exp ~2)

constexpr float WLO   = 0.4375f;
constexpr float WSC   = 2048.0f;            // 256 bins over width 0.125
constexpr float LOG2E = 1.4426950408889634f;

// monotone total-order transform for float bits
__device__ __forceinline__ unsigned u_of_bits(unsigned b) {
    return (b & 0x80000000u) ? ~b : (b | 0x80000000u);
}

__global__ __launch_bounds__(THREADS, 3)
void wdrop_kernel(const float* __restrict__ in, float* __restrict__ out)
{
    __shared__ unsigned hist[NB];
    __shared__ unsigned long long cand[CAND_CAP];
    __shared__ unsigned long long cand2[C2_CAP];
    __shared__ unsigned cand_n, m_n;
    __shared__ float    s_redf[NWARP];
    __shared__ unsigned s_redu[NWARP];
    __shared__ unsigned s_bin, s_rank, s_found;
    __shared__ float    s_max, s_inv;
    __shared__ unsigned long long s_thr;
    __shared__ unsigned long long s_pref;
    __shared__ unsigned s_rrem;

    const int t    = threadIdx.x;
    const int lane = t & 31;
    const int warp = t >> 5;

    const long long row = blockIdx.x;
    const float4* __restrict__ in4  = reinterpret_cast<const float4*>(in  + row * (long long)N);
    float4*       __restrict__ out4 = reinterpret_cast<float4*>      (out + row * (long long)N);

    if (t < NB) hist[t] = 0u;
    if (t == 0) { cand_n = 0u; m_n = 0u; s_found = 0u; }
    __syncthreads();

    // ---- fused pass 1: load, max, below-count, window hist + key pool ----
    float4 xs[VEC];
#pragma unroll
    for (int j = 0; j < VEC; j++) xs[j] = in4[t + THREADS * j];

    float vmax = -3.4e38f;
    unsigned below = 0;
#pragma unroll
    for (int j = 0; j < VEC; j++) {
        float vv[4] = {xs[j].x, xs[j].y, xs[j].z, xs[j].w};
#pragma unroll
        for (int c = 0; c < 4; c++) {
            float val = vv[c];
            vmax = fmaxf(vmax, val);
            below += (val < WLO) ? 1u : 0u;
            int b = __float2int_rd(fmaf(val, WSC, -WLO * WSC));
            if ((unsigned)b < (unsigned)NB) {
                atomicAdd(&hist[b], 1u);
                unsigned p = atomicAdd(&cand_n, 1u);
                if (p < (unsigned)CAND_CAP) {
                    unsigned idx = (unsigned)(4 * (t + THREADS * j) + c);
                    cand[p] = ((unsigned long long)__float_as_uint(val) << 12)
                            | (unsigned long long)idx;
                }
            }
        }
    }
#pragma unroll
    for (int o = 16; o; o >>= 1) {
        vmax   = fmaxf(vmax, __shfl_xor_sync(0xffffffffu, vmax, o));
        below += __shfl_xor_sync(0xffffffffu, below, o);
    }
    if (lane == 0) { s_redf[warp] = vmax; s_redu[warp] = below; }
    __syncthreads();

    // ---- warp 0: combine reductions, scan histogram, find threshold key ----
    if (warp == 0) {
        float    m = (lane < NWARP) ? s_redf[lane] : -3.4e38f;
        unsigned b = (lane < NWARP) ? s_redu[lane] : 0u;
#pragma unroll
        for (int o = 16; o; o >>= 1) {
            m  = fmaxf(m, __shfl_xor_sync(0xffffffffu, m, o));
            b += __shfl_xor_sync(0xffffffffu, b, o);
        }
        if (lane == 0) s_max = m;

        unsigned c8[8]; unsigned sum = 0;
#pragma unroll
        for (int i = 0; i < 8; i++) { c8[i] = hist[lane * 8 + i]; sum += c8[i]; }
        unsigned inc = sum;
#pragma unroll
        for (int o = 1; o < 32; o <<= 1) {
            unsigned nn = __shfl_up_sync(0xffffffffu, inc, o);
            if (lane >= o) inc += nn;
        }
        unsigned c = b + inc - sum;
#pragma unroll
        for (int i = 0; i < 8; i++) {
            unsigned cc = c8[i];
            if (c <= (unsigned)KDROP && (unsigned)KDROP < c + cc) {
                s_bin = (unsigned)(lane * 8 + i);
                s_rank = (unsigned)KDROP - c;
                if (cand_n <= (unsigned)CAND_CAP) s_found = 1u;
            }
            c += cc;
        }
        __syncwarp();
        if (s_found) {
            unsigned bstar = s_bin, rstar = s_rank;
            unsigned cn = min(cand_n, (unsigned)CAND_CAP);
            for (unsigned q = lane; q < cn; q += 32) {
                unsigned long long k = cand[q];
                float v = __uint_as_float((unsigned)(k >> 12));
                int bb = __float2int_rd(fmaf(v, WSC, -WLO * WSC));
                if ((unsigned)bb == bstar) {
                    unsigned p = atomicAdd(&m_n, 1u);
                    if (p < (unsigned)C2_CAP) cand2[p] = k;
                }
            }
            __syncwarp();
            unsigned mn = m_n;
            if (mn <= (unsigned)C2_CAP) {
                if (lane < mn) {
                    unsigned long long k = cand2[lane];
                    unsigned rk = 0;
                    for (unsigned i = 0; i < mn; i++) rk += (cand2[i] < k) ? 1u : 0u;
                    if (rk == rstar) s_thr = k;
                }
            } else {
                if (lane == 0) s_found = 0u;   // overflow -> exact fallback
            }
        }
    }
    __syncthreads();

    // ---- exact fallback: 6-level radix-select on monotone keys (cold) ----
    if (!s_found) {
        if (t == 0) { s_pref = 0ull; s_rrem = (unsigned)KDROP; }
        const int shifts[6] = {36, 28, 20, 12, 6, 0};
        const int widths[6] = {256, 256, 256, 256, 64, 64};
        unsigned long long mask = 0ull;
#pragma unroll 1
        for (int L = 0; L < 6; L++) {
            if (t < widths[L]) hist[t] = 0u;
            __syncthreads();
            unsigned long long pref = s_pref;
#pragma unroll 1
            for (int j = 0; j < VEC; j++) {
                float vv[4] = {xs[j].x, xs[j].y, xs[j].z, xs[j].w};
#pragma unroll 1
                for (int c = 0; c < 4; c++) {
                    unsigned idx = (unsigned)(4 * (t + THREADS * j) + c);
                    unsigned long long K =
                        ((unsigned long long)u_of_bits(__float_as_uint(vv[c])) << 12)
                      | (unsigned long long)idx;
                    if ((K & mask) == pref)
                        atomicAdd(&hist[(unsigned)(K >> shifts[L]) & (unsigned)(widths[L] - 1)], 1u);
                }
            }
            __syncthreads();
            if (t == 0) {
                unsigned r = s_rrem, acc = 0;
                for (int i = 0; i < widths[L]; i++) {
                    unsigned cc = hist[i];
                    if (acc <= r && r < acc + cc) {
                        s_pref = pref | ((unsigned long long)i << shifts[L]);
                        s_rrem = r - acc;
                        break;
                    }
                    acc += cc;
                }
            }
            mask |= (unsigned long long)(widths[L] - 1) << shifts[L];
            __syncthreads();
        }
        if (t == 0) {
            unsigned long long pref = s_pref;
            unsigned uu = (unsigned)(pref >> 12);
            unsigned bits = (uu & 0x80000000u) ? (uu ^ 0x80000000u) : ~uu;
            s_thr = ((unsigned long long)bits << 12) | (pref & 0xFFFull);
        }
        __syncthreads();
    }

    const unsigned long long thr = s_thr;
    const float    thr_val = __uint_as_float((unsigned)(thr >> 12));
    const unsigned thr_idx = (unsigned)(thr & 0xFFFull);
    const float    mC      = -s_max * LOG2E;

    // ---- hot path: single-compare keep, exp2, sum ----
    float lsum = 0.0f;
#pragma unroll
    for (int j = 0; j < VEC; j++) {
        float vv[4] = {xs[j].x, xs[j].y, xs[j].z, xs[j].w};
        float ee[4];
#pragma unroll
        for (int c = 0; c < 4; c++) {
            float val = vv[c];
            unsigned idx = (unsigned)(4 * (t + THREADS * j) + c);
            bool keep = (val > thr_val) || (val == thr_val && idx >= thr_idx);
            float e = keep ? exp2f(fmaf(val, LOG2E, mC)) : 0.0f;
            ee[c] = e;
            lsum += e;
        }
        xs[j].x = ee[0]; xs[j].y = ee[1]; xs[j].z = ee[2]; xs[j].w = ee[3];
    }
#pragma unroll
    for (int o = 16; o; o >>= 1) lsum += __shfl_xor_sync(0xffffffffu, lsum, o);
    if (lane == 0) s_redf[warp] = lsum;
    __syncthreads();
    if (warp == 0) {
        float s = (lane < NWARP) ? s_redf[lane] : 0.0f;
#pragma unroll
        for (int o = 16; o; o >>= 1) s += __shfl_xor_sync(0xffffffffu, s, o);
        if (lane == 0) s_inv = 1.0f / s;
    }
    __syncthreads();
    const float inv = s_inv;

    // ---- scaled store from registers ----
#pragma unroll
    for (int j = 0; j < VEC; j++) {
        float4 o4 = {xs[j].x * inv, xs[j].y * inv, xs[j].z * inv, xs[j].w * inv};
        out4[t + THREADS * j] = o4;
    }
}

} // anonymous namespace

extern "C" void kernel_launch(void* const* d_in, const int* in_sizes, int n_in,
                              void* d_out, int out_size)
{
    (void)n_in; (void)in_sizes;
    const float* w = (const float*)d_in[0];
    float* outp = (float*)d_out;
    int rows = out_size / N;            // 8192
    wdrop_kernel<<<rows, THREADS>>>(w, outp);
}

// round 5
// speedup vs baseline: 1.1083x; 1.1083x over previous
#include <cuda_runtime.h>
#include <cuda_bf16.h>
#include <stdint.h>

// WeightsDropout: per row of [8192,1,4096] f32, zero the 2048 smallest
// (stable-argsort tie-break by index), softmax over survivors.
//
// One CTA (1024 thr) per row; 1 float4 per thread; 2 CTAs/SM (full occ).
// Exact selection: b = floor(fma(val, 2048, -896)) gives below-count (b<0),
// window membership (0<=b<256 ~ [0.4375,0.5625), 12.5% of uniform data),
// and the histogram bin in one FFMA+F2I. Scan finds the rank-2048 bin;
// a second cheap pass gathers that bin's ~2 keys (bits<<12|idx == stable
// sort order); warp 0 ranks them -> exact threshold key; hot path is a
// single (val,idx) compare. Cold exact fallback: radix-select on keys.

namespace {

constexpr int N       = 4096;
constexpr int KDROP   = 2048;
constexpr int THREADS = 1024;
constexpr int NWARP   = THREADS / 32;    // 32
constexpr int NB      = 256;
constexpr int C2_CAP  = 64;

constexpr float WSC   = 2048.0f;         // 256 bins over [0.4375, 0.5625)
constexpr float WOFF  = -896.0f;         // -0.4375 * 2048
constexpr float LOG2E = 1.4426950408889634f;

__device__ __forceinline__ unsigned u_of_bits(unsigned b) {
    return (b & 0x80000000u) ? ~b : (b | 0x80000000u);
}

__global__ __launch_bounds__(THREADS, 2)
void wdrop_kernel(const float* __restrict__ in, float* __restrict__ out)
{
    __shared__ unsigned hist[NB];
    __shared__ unsigned long long cand2[C2_CAP];
    __shared__ unsigned m_n;
    __shared__ float    s_redf[NWARP];
    __shared__ unsigned s_redu[NWARP];
    __shared__ unsigned s_bin, s_rank, s_found, s_ok;
    __shared__ float    s_max, s_inv;
    __shared__ unsigned long long s_thr;
    __shared__ unsigned long long s_pref;
    __shared__ unsigned s_rrem;

    const int t    = threadIdx.x;
    const int lane = t & 31;
    const int warp = t >> 5;

    const long long row = blockIdx.x;
    const float4* __restrict__ in4  = reinterpret_cast<const float4*>(in  + row * (long long)N);
    float4*       __restrict__ out4 = reinterpret_cast<float4*>      (out + row * (long long)N);

    if (t < NB) hist[t] = 0u;
    if (t == 0) { m_n = 0u; s_found = 0u; s_ok = 0u; }
    __syncthreads();

    // ---- pass 1: load 4 elems, max, below-count, window histogram ----
    float4 x = in4[t];
    float vv[4] = {x.x, x.y, x.z, x.w};

    float vmax = -3.4e38f;
    unsigned below = 0;
#pragma unroll
    for (int c = 0; c < 4; c++) {
        float val = vv[c];
        vmax = fmaxf(vmax, val);
        int b = __float2int_rd(fmaf(val, WSC, WOFF));
        below += (b < 0) ? 1u : 0u;
        if ((unsigned)b < (unsigned)NB) atomicAdd(&hist[b], 1u);
    }
#pragma unroll
    for (int o = 16; o; o >>= 1) {
        vmax   = fmaxf(vmax, __shfl_xor_sync(0xffffffffu, vmax, o));
        below += __shfl_xor_sync(0xffffffffu, below, o);
    }
    if (lane == 0) { s_redf[warp] = vmax; s_redu[warp] = below; }
    __syncthreads();

    // ---- warp 0: combine reductions; scan histogram for rank-KDROP bin ----
    if (warp == 0) {
        float    m = s_redf[lane];
        unsigned b = s_redu[lane];
#pragma unroll
        for (int o = 16; o; o >>= 1) {
            m  = fmaxf(m, __shfl_xor_sync(0xffffffffu, m, o));
            b += __shfl_xor_sync(0xffffffffu, b, o);
        }
        if (lane == 0) s_max = m;

        unsigned c8[8]; unsigned sum = 0;
#pragma unroll
        for (int i = 0; i < 8; i++) { c8[i] = hist[lane * 8 + i]; sum += c8[i]; }
        unsigned inc = sum;
#pragma unroll
        for (int o = 1; o < 32; o <<= 1) {
            unsigned nn = __shfl_up_sync(0xffffffffu, inc, o);
            if (lane >= o) inc += nn;
        }
        unsigned c = b + inc - sum;
#pragma unroll
        for (int i = 0; i < 8; i++) {
            unsigned cc = c8[i];
            if (c <= (unsigned)KDROP && (unsigned)KDROP < c + cc) {
                s_bin = (unsigned)(lane * 8 + i);
                s_rank = (unsigned)KDROP - c;
                s_found = 1u;
            }
            c += cc;
        }
    }
    __syncthreads();

    if (s_found) {
        // ---- pass 2: gather boundary-bin keys (~2 per row) ----
        const unsigned bstar = s_bin;
#pragma unroll
        for (int c = 0; c < 4; c++) {
            float val = vv[c];
            int b = __float2int_rd(fmaf(val, WSC, WOFF));
            if ((unsigned)b == bstar) {
                unsigned p = atomicAdd(&m_n, 1u);
                if (p < (unsigned)C2_CAP) {
                    unsigned idx = (unsigned)(4 * t + c);
                    cand2[p] = ((unsigned long long)__float_as_uint(val) << 12)
                             | (unsigned long long)idx;
                }
            }
        }
        __syncthreads();
        // ---- warp 0: exact threshold key = in-bin rank s_rank ----
        if (warp == 0) {
            unsigned mn = m_n, rstar = s_rank;
            if (mn <= (unsigned)C2_CAP) {
                if (lane < mn) {
                    unsigned long long k = cand2[lane];
                    unsigned rk = 0;
                    for (unsigned i = 0; i < mn; i++) rk += (cand2[i] < k) ? 1u : 0u;
                    if (rk == rstar) { s_thr = k; s_ok = 1u; }
                }
            }
        }
        __syncthreads();
    }

    // ---- cold exact fallback: radix-select on monotone 44-bit keys ----
    if (!s_ok) {
        if (t == 0) { s_pref = 0ull; s_rrem = (unsigned)KDROP; }
        const int shifts[6] = {36, 28, 20, 12, 6, 0};
        const int widths[6] = {256, 256, 256, 256, 64, 64};
        unsigned long long mask = 0ull;
#pragma unroll 1
        for (int L = 0; L < 6; L++) {
            if (t < widths[L]) hist[t] = 0u;
            __syncthreads();
            unsigned long long pref = s_pref;
#pragma unroll 1
            for (int c = 0; c < 4; c++) {
                unsigned idx = (unsigned)(4 * t + c);
                unsigned long long K =
                    ((unsigned long long)u_of_bits(__float_as_uint(vv[c])) << 12)
                  | (unsigned long long)idx;
                if ((K & mask) == pref)
                    atomicAdd(&hist[(unsigned)(K >> shifts[L]) & (unsigned)(widths[L] - 1)], 1u);
            }
            __syncthreads();
            if (t == 0) {
                unsigned r = s_rrem, acc = 0;
                for (int i = 0; i < widths[L]; i++) {
                    unsigned cc = hist[i];
                    if (acc <= r && r < acc + cc) {
                        s_pref = pref | ((unsigned long long)i << shifts[L]);
                        s_rrem = r - acc;
                        break;
                    }
                    acc += cc;
                }
            }
            mask |= (unsigned long long)(widths[L] - 1) << shifts[L];
            __syncthreads();
        }
        if (t == 0) {
            unsigned long long pref = s_pref;
            unsigned uu = (unsigned)(pref >> 12);
            unsigned bits = (uu & 0x80000000u) ? (uu ^ 0x80000000u) : ~uu;
            s_thr = ((unsigned long long)bits << 12) | (pref & 0xFFFull);
        }
        __syncthreads();
    }

    const unsigned long long thr = s_thr;
    const unsigned thr_bits = (unsigned)(thr >> 12);
    const unsigned thr_idx  = (unsigned)(thr & 0xFFFull);
    const float    thr_val  = __uint_as_float(thr_bits);
    const float    mC       = -s_max * LOG2E;

    // ---- pass 3: single-compare keep, exp2(fma), sum ----
    float ee[4];
    float lsum = 0.0f;
#pragma unroll
    for (int c = 0; c < 4; c++) {
        float val = vv[c];
        unsigned idx = (unsigned)(4 * t + c);
        bool keep = (val > thr_val) || (val == thr_val && idx >= thr_idx);
        float e = keep ? exp2f(fmaf(val, LOG2E, mC)) : 0.0f;
        ee[c] = e;
        lsum += e;
    }
#pragma unroll
    for (int o = 16; o; o >>= 1) lsum += __shfl_xor_sync(0xffffffffu, lsum, o);
    if (lane == 0) s_redf[warp] = lsum;
    __syncthreads();
    if (warp == 0) {
        float s = s_redf[lane];
#pragma unroll
        for (int o = 16; o; o >>= 1) s += __shfl_xor_sync(0xffffffffu, s, o);
        if (lane == 0) s_inv = 1.0f / s;
    }
    __syncthreads();
    const float inv = s_inv;

    float4 o4 = {ee[0] * inv, ee[1] * inv, ee[2] * inv, ee[3] * inv};
    out4[t] = o4;
}

} // anonymous namespace

extern "C" void kernel_launch(void* const* d_in, const int* in_sizes, int n_in,
                              void* d_out, int out_size)
{
    (void)n_in; (void)in_sizes;
    const float* w = (const float*)d_in[0];
    float* outp = (float*)d_out;
    int rows = out_size / N;            // 8192
    wdrop_kernel<<<rows, THREADS>>>(w, outp);
}

// round 6
// speedup vs baseline: 1.1129x; 1.0041x over previous
#include <cuda_runtime.h>
#include <cuda_bf16.h>
#include <stdint.h>

// WeightsDropout: per row of [8192,1,4096] f32, zero the 2048 smallest
// (stable-argsort tie-break by index), softmax over survivors.
//
// One CTA (256 thr) per row, 16 elems/thread in registers, 6 CTAs/SM.
// b = floor(fma(val,4096,-1920)) gives below-count (b<0) and the 256-bin
// histogram over [0.46875, 0.53125) (rank-2048 boundary is ~0.5 +- 4 sigma
// for uniform rows). Every warp redundantly scans the histogram and ranks
// the ~1-2 boundary-bin keys (bits<<12|idx == stable-sort order), so only
// 4 CTA barriers remain. Hot path = one (val,idx) compare + exp2.
// Exact cold fallback: 6-level radix-select on monotone 44-bit keys.

namespace {

constexpr int N       = 4096;
constexpr int KDROP   = 2048;
constexpr int THREADS = 256;
constexpr int VEC     = 4;               // float4 per thread (16 elems)
constexpr int NWARP   = THREADS / 32;    // 8
constexpr int NB      = 256;
constexpr int C2_CAP  = 32;              // boundary-bin keys (exp ~1)

constexpr float WSC   = 4096.0f;         // 256 bins over [0.46875, 0.53125)
constexpr float WOFF  = -1920.0f;        // -0.46875 * 4096
constexpr float LOG2E = 1.4426950408889634f;

__device__ __forceinline__ unsigned u_of_bits(unsigned b) {
    return (b & 0x80000000u) ? ~b : (b | 0x80000000u);
}

__global__ __launch_bounds__(THREADS, 6)
void wdrop_kernel(const float* __restrict__ in, float* __restrict__ out)
{
    __shared__ unsigned hist[NB];
    __shared__ unsigned long long cand2[C2_CAP];
    __shared__ unsigned m_n;
    __shared__ int      s_maxi;
    __shared__ unsigned s_below;
    __shared__ float    s_redf[NWARP];
    __shared__ unsigned long long s_thr;
    __shared__ unsigned long long s_pref;
    __shared__ unsigned s_rrem;

    const int t    = threadIdx.x;
    const int lane = t & 31;
    const int warp = t >> 5;

    const long long row = blockIdx.x;
    const float4* __restrict__ in4  = reinterpret_cast<const float4*>(in  + row * (long long)N);
    float4*       __restrict__ out4 = reinterpret_cast<float4*>      (out + row * (long long)N);

    hist[t] = 0u;                          // NB == THREADS
    if (t == 0) { m_n = 0u; s_maxi = 0; s_below = 0u; }
    __syncthreads();                       // --- barrier 1 (init)

    // ---- pass 1: load, max, below-count, window histogram ----
    float4 xs[VEC];
#pragma unroll
    for (int j = 0; j < VEC; j++) xs[j] = in4[t + THREADS * j];

    float vmax = 0.0f;                     // inputs are positive
    unsigned below = 0;
#pragma unroll
    for (int j = 0; j < VEC; j++) {
        float vv[4] = {xs[j].x, xs[j].y, xs[j].z, xs[j].w};
#pragma unroll
        for (int c = 0; c < 4; c++) {
            float val = vv[c];
            vmax = fmaxf(vmax, val);
            int b = __float2int_rd(fmaf(val, WSC, WOFF));
            below += (b < 0) ? 1u : 0u;
            if ((unsigned)b < (unsigned)NB) atomicAdd(&hist[b], 1u);
        }
    }
#pragma unroll
    for (int o = 16; o; o >>= 1) {
        vmax   = fmaxf(vmax, __shfl_xor_sync(0xffffffffu, vmax, o));
        below += __shfl_xor_sync(0xffffffffu, below, o);
    }
    if (lane == 0) {
        atomicMax(&s_maxi, __float_as_int(vmax));   // positive floats: int order == float order
        atomicAdd(&s_below, below);
    }
    __syncthreads();                       // --- barrier 2 (hist/max/below ready)

    const float m  = __int_as_float(s_maxi);
    const unsigned base = s_below;

    // ---- every warp scans the histogram (redundant; no extra barrier) ----
    unsigned bstar = 0, rstar = 0;
    bool found;
    {
        unsigned c8[8]; unsigned sum = 0;
#pragma unroll
        for (int i = 0; i < 8; i++) { c8[i] = hist[lane * 8 + i]; sum += c8[i]; }
        unsigned inc = sum;
#pragma unroll
        for (int o = 1; o < 32; o <<= 1) {
            unsigned nn = __shfl_up_sync(0xffffffffu, inc, o);
            if (lane >= o) inc += nn;
        }
        unsigned c = base + inc - sum;
        unsigned lbin = 0, lrank = 0; bool lfound = false;
#pragma unroll
        for (int i = 0; i < 8; i++) {
            unsigned cc = c8[i];
            if (c <= (unsigned)KDROP && (unsigned)KDROP < c + cc) {
                lbin = (unsigned)(lane * 8 + i);
                lrank = (unsigned)KDROP - c;
                lfound = true;
            }
            c += cc;
        }
        unsigned msk = __ballot_sync(0xffffffffu, lfound);
        found = (msk != 0u);
        if (found) {
            int src = __ffs(msk) - 1;
            bstar = __shfl_sync(0xffffffffu, lbin,  src);
            rstar = __shfl_sync(0xffffffffu, lrank, src);
        }
    }

    // ---- gather boundary-bin keys; every warp ranks them ----
    unsigned long long thr = 0ull;
    bool have_thr = false;
    if (found) {                           // uniform across CTA
#pragma unroll
        for (int j = 0; j < VEC; j++) {
            float vv[4] = {xs[j].x, xs[j].y, xs[j].z, xs[j].w};
#pragma unroll
            for (int c = 0; c < 4; c++) {
                float val = vv[c];
                int b = __float2int_rd(fmaf(val, WSC, WOFF));
                if ((unsigned)b == bstar) {
                    unsigned p = atomicAdd(&m_n, 1u);
                    if (p < (unsigned)C2_CAP) {
                        unsigned idx = (unsigned)(4 * (t + THREADS * j) + c);
                        cand2[p] = ((unsigned long long)__float_as_uint(val) << 12)
                                 | (unsigned long long)idx;
                    }
                }
            }
        }
        __syncthreads();                   // --- barrier 3 (cand2 ready)
        unsigned mn = m_n;
        if (mn <= (unsigned)C2_CAP) {      // uniform
            unsigned long long k = 0ull; bool hit = false;
            if (lane < mn) {
                k = cand2[lane];
                unsigned rk = 0;
                for (unsigned i = 0; i < mn; i++) rk += (cand2[i] < k) ? 1u : 0u;
                hit = (rk == rstar);
            }
            unsigned msk = __ballot_sync(0xffffffffu, hit);
            int src = __ffs(msk) - 1;      // exactly one hit (keys distinct)
            thr = __shfl_sync(0xffffffffu, k, src);
            have_thr = true;
        }
    }

    // ---- exact cold fallback: radix-select on monotone 44-bit keys ----
    if (!have_thr) {                       // uniform across CTA
        if (t == 0) { s_pref = 0ull; s_rrem = (unsigned)KDROP; }
        const int shifts[6] = {36, 28, 20, 12, 6, 0};
        const int widths[6] = {256, 256, 256, 256, 64, 64};
        unsigned long long mask = 0ull;
#pragma unroll 1
        for (int L = 0; L < 6; L++) {
            if (t < widths[L]) hist[t] = 0u;
            __syncthreads();
            unsigned long long pref = s_pref;
#pragma unroll 1
            for (int j = 0; j < VEC; j++) {
                float vv[4] = {xs[j].x, xs[j].y, xs[j].z, xs[j].w};
#pragma unroll 1
                for (int c = 0; c < 4; c++) {
                    unsigned idx = (unsigned)(4 * (t + THREADS * j) + c);
                    unsigned long long K =
                        ((unsigned long long)u_of_bits(__float_as_uint(vv[c])) << 12)
                      | (unsigned long long)idx;
                    if ((K & mask) == pref)
                        atomicAdd(&hist[(unsigned)(K >> shifts[L]) & (unsigned)(widths[L] - 1)], 1u);
                }
            }
            __syncthreads();
            if (t == 0) {
                unsigned r = s_rrem, acc = 0;
                for (int i = 0; i < widths[L]; i++) {
                    unsigned cc = hist[i];
                    if (acc <= r && r < acc + cc) {
                        s_pref = pref | ((unsigned long long)i << shifts[L]);
                        s_rrem = r - acc;
                        break;
                    }
                    acc += cc;
                }
            }
            mask |= (unsigned long long)(widths[L] - 1) << shifts[L];
            __syncthreads();
        }
        if (t == 0) {
            unsigned long long pref = s_pref;
            unsigned uu = (unsigned)(pref >> 12);
            unsigned bits = (uu & 0x80000000u) ? (uu ^ 0x80000000u) : ~uu;
            s_thr = ((unsigned long long)bits << 12) | (pref & 0xFFFull);
        }
        __syncthreads();
        thr = s_thr;
    }

    const float    thr_val = __uint_as_float((unsigned)(thr >> 12));
    const unsigned thr_idx = (unsigned)(thr & 0xFFFull);
    const float    mC      = -m * LOG2E;

    // ---- pass 3: single-compare keep, exp2, sum ----
    float lsum = 0.0f;
#pragma unroll
    for (int j = 0; j < VEC; j++) {
        float vv[4] = {xs[j].x, xs[j].y, xs[j].z, xs[j].w};
        float ee[4];
#pragma unroll
        for (int c = 0; c < 4; c++) {
            float val = vv[c];
            unsigned idx = (unsigned)(4 * (t + THREADS * j) + c);
            bool keep = (val > thr_val) || (val == thr_val && idx >= thr_idx);
            float e = keep ? exp2f(fmaf(val, LOG2E, mC)) : 0.0f;
            ee[c] = e;
            lsum += e;
        }
        xs[j].x = ee[0]; xs[j].y = ee[1]; xs[j].z = ee[2]; xs[j].w = ee[3];
    }
#pragma unroll
    for (int o = 16; o; o >>= 1) lsum += __shfl_xor_sync(0xffffffffu, lsum, o);
    if (lane == 0) s_redf[warp] = lsum;
    __syncthreads();                       // --- barrier 4 (partials ready)

    float s = s_redf[0];
#pragma unroll
    for (int i = 1; i < NWARP; i++) s += s_redf[i];
    const float inv = 1.0f / s;

    // ---- scaled store from registers ----
#pragma unroll
    for (int j = 0; j < VEC; j++) {
        float4 o4 = {xs[j].x * inv, xs[j].y * inv, xs[j].z * inv, xs[j].w * inv};
        out4[t + THREADS * j] = o4;
    }
}

} // anonymous namespace

extern "C" void kernel_launch(void* const* d_in, const int* in_sizes, int n_in,
                              void* d_out, int out_size)
{
    (void)n_in; (void)in_sizes;
    const float* w = (const float*)d_in[0];
    float* outp = (float*)d_out;
    int rows = out_size / N;            // 8192
    wdrop_kernel<<<rows, THREADS>>>(w, outp);
}